// round 2
// baseline (speedup 1.0000x reference)
#include <cuda_runtime.h>
#include <math.h>

#define B    16384
#define D    1024
#define KC   15
#define C    1000
#define NMOD 3

// ---------------- scratch (device globals; no allocation) ----------------
__device__ float g_cnorm[NMOD][KC];     // 1/clamped centroid norms
__device__ float g_avg[NMOD][B];        // avg similarity per row
__device__ int   g_assign[NMOD][B];     // argmax cluster per row
__device__ float g_rmax[B];             // softmax row max
__device__ float g_rsum[B];             // softmax row sum-exp
__device__ float g_segsum[NMOD][KC][C]; // per-cluster prob sums
__device__ float g_counts[NMOD][KC];
__device__ float g_attr;                // sum over all (mod,row) of w*(1-avg)
__device__ float g_div;                 // sum of gated negative entropies

// ---------------- init: zero accumulators ----------------
__global__ void init_kernel() {
    int i = blockIdx.x * blockDim.x + threadIdx.x;
    int total = NMOD * KC * C;
    if (i < total) ((float*)g_segsum)[i] = 0.f;
    if (i == 0) { g_attr = 0.f; g_div = 0.f; }
}

// ---------------- centroid inverse norms (45 rows of 1024) ----------------
__global__ void cnorm_kernel(const float* __restrict__ c0,
                             const float* __restrict__ c1,
                             const float* __restrict__ c2) {
    int b = blockIdx.x;           // 0..44
    int mod = b / KC, k = b % KC;
    const float* cen = mod == 0 ? c0 : (mod == 1 ? c1 : c2);
    const float4* row = (const float4*)(cen + (size_t)k * D);
    float s = 0.f;
    for (int i = threadIdx.x; i < D / 4; i += blockDim.x) {
        float4 v = row[i];
        s += v.x * v.x + v.y * v.y + v.z * v.z + v.w * v.w;
    }
    __shared__ float sm[256];
    sm[threadIdx.x] = s; __syncthreads();
    for (int o = 128; o > 0; o >>= 1) {
        if (threadIdx.x < o) sm[threadIdx.x] += sm[threadIdx.x + o];
        __syncthreads();
    }
    if (threadIdx.x == 0)
        g_cnorm[mod][k] = 1.f / fmaxf(sqrtf(sm[0]), 1e-12f);
}

// ---------------- similarities: avg_sim + argmax per (modality,row) -------
// 256 threads, each thread owns 4 fixed columns -> 15 centroid float4s live
// in registers for the whole block. 16 partials (15 dots + normsq) reduced
// with a multi-value butterfly (16 shuffles/row/warp).
#define SIM_ROWS 32
__global__ __launch_bounds__(256) void sim_kernel(
    const float* __restrict__ f0, const float* __restrict__ f1, const float* __restrict__ f2,
    const float* __restrict__ c0, const float* __restrict__ c1, const float* __restrict__ c2) {
    int mod = blockIdx.y;
    const float* fea = mod == 0 ? f0 : (mod == 1 ? f1 : f2);
    const float* cen = mod == 0 ? c0 : (mod == 1 ? c1 : c2);
    int tid = threadIdx.x;
    int lane = tid & 31, warp = tid >> 5;
    int col = tid * 4;

    float4 cw[KC];
#pragma unroll
    for (int k = 0; k < KC; k++)
        cw[k] = *(const float4*)(cen + (size_t)k * D + col);

    __shared__ float stage[2][8][16];
    __shared__ float tot[2][16];
    __shared__ float s_cn[KC];
    if (tid < KC) s_cn[tid] = g_cnorm[mod][tid];
    __syncthreads();

    // value index held by this lane after the butterfly: bit-reversed nibble
    int vidx = ((lane & 1) ? 8 : 0) | ((lane & 2) ? 4 : 0) |
               ((lane & 4) ? 2 : 0) | ((lane & 8) ? 1 : 0);

    int row0 = blockIdx.x * SIM_ROWS;
    for (int rr = 0; rr < SIM_ROWS; rr++) {
        int row = row0 + rr;
        float4 f = *(const float4*)(fea + (size_t)row * D + col);
        float v[16];
        v[15] = f.x * f.x + f.y * f.y + f.z * f.z + f.w * f.w;
#pragma unroll
        for (int k = 0; k < KC; k++)
            v[k] = f.x * cw[k].x + f.y * cw[k].y + f.z * cw[k].z + f.w * cw[k].w;

        // multi-value warp reduction: 16 values across 32 lanes
#pragma unroll
        for (int s = 0; s < 4; s++) {
            int d2 = 1 << s;
            int half = 8 >> s;
            bool hi = (lane & d2) != 0;
#pragma unroll
            for (int i = 0; i < half; i++) {
                float send = hi ? v[i] : v[i + half];
                float recv = __shfl_xor_sync(0xffffffffu, send, d2);
                v[i] = (hi ? v[i + half] : v[i]) + recv;
            }
        }
        v[0] += __shfl_xor_sync(0xffffffffu, v[0], 16);

        int par = rr & 1;
        if (lane < 16) stage[par][warp][vidx] = v[0];
        __syncthreads();
        if (tid < 16) {
            float s = 0.f;
#pragma unroll
            for (int w = 0; w < 8; w++) s += stage[par][w][tid];
            tot[par][tid] = s;
        }
        __syncthreads();
        if (tid == 0) {
            float fin = 1.f / fmaxf(sqrtf(tot[par][15]), 1e-12f);
            float best = -1e30f; int bi = 0; float sum = 0.f;
#pragma unroll
            for (int k = 0; k < KC; k++) {
                float sim = tot[par][k] * fin * s_cn[k];
                sum += sim;
                if (sim > best) { best = sim; bi = k; }
            }
            g_avg[mod][row] = sum * (1.0f / KC);
            g_assign[mod][row] = bi;
        }
    }
}

// ---------------- softmax stats + copy out -> d_out ----------------
// warp-per-row; row kept in registers; single pass over gmem.
__global__ __launch_bounds__(256) void softmax_kernel(const float* __restrict__ outp,
                                                      float* __restrict__ ocopy) {
    int warp = threadIdx.x >> 5, lane = threadIdx.x & 31;
    int row = blockIdx.x * 8 + warp;
    const float* r = outp + (size_t)row * C;
    float* w = ocopy + (size_t)row * C;
    float arr[32];
    float m = -INFINITY;
#pragma unroll
    for (int i = 0; i < 32; i++) {
        int j = lane + i * 32;
        if (j < C) { float x = r[j]; arr[i] = x; w[j] = x; m = fmaxf(m, x); }
    }
#pragma unroll
    for (int o = 16; o > 0; o >>= 1) m = fmaxf(m, __shfl_xor_sync(0xffffffffu, m, o));
    float s = 0.f;
#pragma unroll
    for (int i = 0; i < 32; i++) {
        int j = lane + i * 32;
        if (j < C) s += expf(arr[i] - m);
    }
#pragma unroll
    for (int o = 16; o > 0; o >>= 1) s += __shfl_xor_sync(0xffffffffu, s, o);
    if (lane == 0) { g_rmax[row] = m; g_rsum[row] = s; }
}

// ---------------- exact k-th order statistic (radix select) + attractive --
__global__ void select_attr_kernel(int rank0) {
    int mod = blockIdx.x;
    const float* avg = g_avg[mod];
    __shared__ unsigned int hist[256];
    __shared__ unsigned int s_prefix;
    __shared__ int s_rank;
    __shared__ float s_thr;
    if (threadIdx.x == 0) { s_prefix = 0u; s_rank = rank0; }
    __syncthreads();

    for (int p = 3; p >= 0; p--) {
        hist[threadIdx.x] = 0u;
        __syncthreads();
        unsigned int mask = (p == 3) ? 0u : (0xFFFFFFFFu << ((p + 1) * 8));
        unsigned int pref = s_prefix;
        for (int i = threadIdx.x; i < B; i += 256) {
            unsigned int u = __float_as_uint(avg[i]);
            u = (u & 0x80000000u) ? ~u : (u | 0x80000000u);  // order-preserving
            if ((u & mask) == (pref & mask))
                atomicAdd(&hist[(u >> (p * 8)) & 255u], 1u);
        }
        __syncthreads();
        if (threadIdx.x == 0) {
            unsigned int cum = 0; int r = s_rank;
            for (int b = 0; b < 256; b++) {
                unsigned int h = hist[b];
                if (cum + h > (unsigned int)r) {
                    s_prefix = pref | ((unsigned int)b << (p * 8));
                    s_rank = r - (int)cum;
                    break;
                }
                cum += h;
            }
        }
        __syncthreads();
    }
    if (threadIdx.x == 0) {
        unsigned int u = s_prefix;
        unsigned int bits = (u & 0x80000000u) ? (u ^ 0x80000000u) : ~u;
        s_thr = __uint_as_float(bits);
    }
    __syncthreads();

    float thr = s_thr;
    float s = 0.f;
    for (int i = threadIdx.x; i < B; i += 256) {
        float a = avg[i];
        float w = 1.f / (1.f + expf(-5.0f * (a - thr)));  // ALPHA = 5.0
        s += w * (1.f - a);
    }
    __shared__ float sm[256];
    sm[threadIdx.x] = s; __syncthreads();
    for (int o = 128; o > 0; o >>= 1) {
        if (threadIdx.x < o) sm[threadIdx.x] += sm[threadIdx.x + o];
        __syncthreads();
    }
    if (threadIdx.x == 0) atomicAdd(&g_attr, sm[0]);
}

// ---------------- cluster counts ----------------
__global__ void counts_kernel() {
    int mod = blockIdx.x;
    __shared__ int cnt[KC];
    if (threadIdx.x < KC) cnt[threadIdx.x] = 0;
    __syncthreads();
    for (int i = threadIdx.x; i < B; i += blockDim.x)
        atomicAdd(&cnt[g_assign[mod][i]], 1);
    __syncthreads();
    if (threadIdx.x < KC) g_counts[mod][threadIdx.x] = (float)cnt[threadIdx.x];
}

// ---------------- segment sums of softmax probs ----------------
// column-tiled; each thread owns one column with 45 exclusive smem slots.
#define SEG_ROWS 128
__global__ __launch_bounds__(256) void seg_kernel(const float* __restrict__ outp) {
    __shared__ float acc[NMOD * KC * 256];   // 46080 B
    int tid = threadIdx.x;
    int c = blockIdx.x * 256 + tid;
    bool valid = c < C;
    for (int j = tid; j < NMOD * KC * 256; j += 256) acc[j] = 0.f;
    __syncthreads();

    int r0 = blockIdx.y * SEG_ROWS;
    for (int rr = 0; rr < SEG_ROWS; rr++) {
        int r = r0 + rr;
        int a0 = g_assign[0][r], a1 = g_assign[1][r], a2 = g_assign[2][r];
        float rm = g_rmax[r];
        float ri = 1.f / g_rsum[r];
        if (valid) {
            float p = expf(outp[(size_t)r * C + c] - rm) * ri;
            acc[a0 * 256 + tid]            += p;
            acc[(KC + a1) * 256 + tid]     += p;
            acc[(2 * KC + a2) * 256 + tid] += p;
        }
    }
    __syncthreads();
    if (valid) {
        for (int j = 0; j < NMOD * KC; j++)
            atomicAdd(&((float*)g_segsum)[(size_t)j * C + c], acc[j * 256 + tid]);
    }
}

// ---------------- gated negative entropy ----------------
__global__ void entropy_kernel() {
    int bk = blockIdx.x;  // 0..44 = mod*15+k
    float cnt = ((float*)g_counts)[bk];
    float inv = 1.f / fmaxf(cnt, 1.f);
    const float* sums = ((float*)g_segsum) + (size_t)bk * C;
    float s = 0.f;
    for (int i = threadIdx.x; i < C; i += 256) {
        float mp = sums[i] * inv;
        s += mp * logf(mp + 1e-8f);
    }
    __shared__ float sm[256];
    sm[threadIdx.x] = s; __syncthreads();
    for (int o = 128; o > 0; o >>= 1) {
        if (threadIdx.x < o) sm[threadIdx.x] += sm[threadIdx.x + o];
        __syncthreads();
    }
    if (threadIdx.x == 0 && cnt >= 3.0f) atomicAdd(&g_div, sm[0]);
}

// ---------------- finalize: loss = LAM_CLUSTER*attr + LAM_DIV*div ---------
__global__ void finalize_kernel(float* dout, long long idx) {
    // LAM_CLUSTER = 6.0 (NOT ALPHA=5.0 — that was the R1 bug), LAM_DIV = 0.1
    dout[idx] = 6.0f * (g_attr / (float)B) + 0.1f * g_div;
}

// ---------------- launch ----------------
extern "C" void kernel_launch(void* const* d_in, const int* in_sizes, int n_in,
                              void* d_out, int out_size) {
    const float* f0 = (const float*)d_in[0];
    const float* f1 = (const float*)d_in[1];
    const float* f2 = (const float*)d_in[2];
    const float* c0 = (const float*)d_in[3];
    const float* c1 = (const float*)d_in[4];
    const float* c2 = (const float*)d_in[5];
    const float* outp = (const float*)d_in[6];
    float* dout = (float*)d_out;
    (void)n_in; (void)in_sizes;

    init_kernel<<<(NMOD * KC * C + 255) / 256, 256>>>();
    cnorm_kernel<<<NMOD * KC, 256>>>(c0, c1, c2);
    sim_kernel<<<dim3(B / SIM_ROWS, NMOD), 256>>>(f0, f1, f2, c0, c1, c2);
    softmax_kernel<<<B / 8, 256>>>(outp, dout);

    int rank0 = B - (int)((double)B * 0.6);   // = 6554, matches int(n*PCT)
    select_attr_kernel<<<NMOD, 256>>>(rank0);
    counts_kernel<<<NMOD, 256>>>();
    seg_kernel<<<dim3((C + 255) / 256, B / SEG_ROWS), 256>>>(outp);
    entropy_kernel<<<NMOD * KC, 256>>>();
    finalize_kernel<<<1, 1>>>(dout, (long long)out_size - 1);
}

// round 3
// speedup vs baseline: 1.1198x; 1.1198x over previous
#include <cuda_runtime.h>
#include <math.h>

#define B    16384
#define D    1024
#define KC   15
#define C    1000
#define NMOD 3

typedef unsigned long long ull;

// ---------------- scratch (device globals; no allocation) ----------------
__device__ float g_cnorm[NMOD][KC];
__device__ float g_avg[NMOD][B];
__device__ int   g_assign[NMOD][B];
__device__ int   g_counts_i[NMOD][KC];
__device__ float g_rmax[B];
__device__ float g_rsum[B];
__device__ float g_segsum[NMOD][KC][C];
__device__ float g_attr;
__device__ float g_div;
__device__ int   g_ticket;

// ---------------- packed f32x2 helpers ----------------
__device__ __forceinline__ ull pack2(float x, float y) {
    ull r; asm("mov.b64 %0,{%1,%2};" : "=l"(r) : "f"(x), "f"(y)); return r;
}
__device__ __forceinline__ float2 unpack2(ull v) {
    float2 o; asm("mov.b64 {%0,%1},%2;" : "=f"(o.x), "=f"(o.y) : "l"(v)); return o;
}
__device__ __forceinline__ ull fma2(ull a, ull b, ull c) {
    ull r; asm("fma.rn.f32x2 %0,%1,%2,%3;" : "=l"(r) : "l"(a), "l"(b), "l"(c)); return r;
}

// ---------------- node 1: centroid norms + zero accumulators --------------
__global__ void cnorm_init_kernel(const float* __restrict__ c0,
                                  const float* __restrict__ c1,
                                  const float* __restrict__ c2) {
    int b = blockIdx.x;           // 0..44
    int mod = b / KC, k = b % KC;
    // zero this block's segsum slice
    float* seg = ((float*)g_segsum) + (size_t)b * C;
    for (int i = threadIdx.x; i < C; i += 256) seg[i] = 0.f;
    if (b == 0) {
        if (threadIdx.x == 0) { g_attr = 0.f; g_div = 0.f; g_ticket = 0; }
        if (threadIdx.x < NMOD * KC) ((int*)g_counts_i)[threadIdx.x] = 0;
    }
    const float* cen = mod == 0 ? c0 : (mod == 1 ? c1 : c2);
    const float4* row = (const float4*)(cen + (size_t)k * D);
    float s = 0.f;
    for (int i = threadIdx.x; i < D / 4; i += 256) {
        float4 v = row[i];
        s += v.x * v.x + v.y * v.y + v.z * v.z + v.w * v.w;
    }
    __shared__ float sm[256];
    sm[threadIdx.x] = s; __syncthreads();
    for (int o = 128; o > 0; o >>= 1) {
        if (threadIdx.x < o) sm[threadIdx.x] += sm[threadIdx.x + o];
        __syncthreads();
    }
    if (threadIdx.x == 0)
        g_cnorm[mod][k] = 1.f / fmaxf(sqrtf(sm[0]), 1e-12f);
}

// ---------------- node 2: softmax stats + copy (float4) ----------------
__global__ __launch_bounds__(256) void softmax_kernel(const float* __restrict__ outp,
                                                      float* __restrict__ ocopy) {
    int warp = threadIdx.x >> 5, lane = threadIdx.x & 31;
    int row = blockIdx.x * 8 + warp;
    const float4* r4 = (const float4*)(outp + (size_t)row * C);
    float4* w4 = (float4*)(ocopy + (size_t)row * C);
    float4 a[8];
    float m = -INFINITY;
#pragma unroll
    for (int i = 0; i < 8; i++) {
        int j = lane + i * 32;
        if (j < C / 4) {
            float4 x = r4[j]; a[i] = x; w4[j] = x;
            m = fmaxf(m, fmaxf(fmaxf(x.x, x.y), fmaxf(x.z, x.w)));
        }
    }
#pragma unroll
    for (int o = 16; o > 0; o >>= 1) m = fmaxf(m, __shfl_xor_sync(0xffffffffu, m, o));
    float s = 0.f;
#pragma unroll
    for (int i = 0; i < 8; i++) {
        int j = lane + i * 32;
        if (j < C / 4)
            s += __expf(a[i].x - m) + __expf(a[i].y - m) + __expf(a[i].z - m) + __expf(a[i].w - m);
    }
#pragma unroll
    for (int o = 16; o > 0; o >>= 1) s += __shfl_xor_sync(0xffffffffu, s, o);
    if (lane == 0) { g_rmax[row] = m; g_rsum[row] = s; }
}

// ---------------- node 3: similarities (phase A/B, f32x2, fused counts) ---
#define SIM_ROWS 32
__global__ __launch_bounds__(256, 2) void sim_kernel(
    const float* __restrict__ f0, const float* __restrict__ f1, const float* __restrict__ f2,
    const float* __restrict__ c0, const float* __restrict__ c1, const float* __restrict__ c2) {
    int mod = blockIdx.y;
    const float* fea = mod == 0 ? f0 : (mod == 1 ? f1 : f2);
    const float* cen = mod == 0 ? c0 : (mod == 1 ? c1 : c2);
    int tid = threadIdx.x;
    int lane = tid & 31, warp = tid >> 5;
    int col = tid * 4;

    ull clo[KC], chi[KC];
#pragma unroll
    for (int k = 0; k < KC; k++) {
        float4 cv = *(const float4*)(cen + (size_t)k * D + col);
        clo[k] = pack2(cv.x, cv.y);
        chi[k] = pack2(cv.z, cv.w);
    }

    __shared__ float stage[SIM_ROWS][8][16];   // 16 KB
    __shared__ float tot[SIM_ROWS][16];        // 2 KB
    __shared__ float s_cn[KC];
    if (tid < KC) s_cn[tid] = g_cnorm[mod][tid];

    // value index held by this lane after the butterfly: bit-reversed nibble
    int vidx = ((lane & 1) ? 8 : 0) | ((lane & 2) ? 4 : 0) |
               ((lane & 4) ? 2 : 0) | ((lane & 8) ? 1 : 0);

    int row0 = blockIdx.x * SIM_ROWS;
    const float4* fp = (const float4*)(fea + (size_t)row0 * D) + tid;
    float4 f = fp[0];

    // -------- phase A: butterfly partials for 32 rows, no syncs --------
    for (int rr = 0; rr < SIM_ROWS; rr++) {
        float4 fn;
        if (rr + 1 < SIM_ROWS) fn = fp[(rr + 1) * (D / 4)];
        ull flo = pack2(f.x, f.y), fhi = pack2(f.z, f.w);

        float v[16];
        {
            ull n2 = fma2(flo, flo, 0ull);
            n2 = fma2(fhi, fhi, n2);
            float2 n = unpack2(n2);
            v[15] = n.x + n.y;
        }
#pragma unroll
        for (int k = 0; k < KC; k++) {
            ull acc = fma2(flo, clo[k], 0ull);
            acc = fma2(fhi, chi[k], acc);
            float2 p = unpack2(acc);
            v[k] = p.x + p.y;
        }

        // multi-value warp reduction: 16 values across 32 lanes
#pragma unroll
        for (int s = 0; s < 4; s++) {
            int d2 = 1 << s;
            int half = 8 >> s;
            bool hi = (lane & d2) != 0;
#pragma unroll
            for (int i = 0; i < half; i++) {
                float send = hi ? v[i] : v[i + half];
                float recv = __shfl_xor_sync(0xffffffffu, send, d2);
                v[i] = (hi ? v[i + half] : v[i]) + recv;
            }
        }
        v[0] += __shfl_xor_sync(0xffffffffu, v[0], 16);

        if (lane < 16) stage[rr][warp][vidx] = v[0];
        f = fn;
    }
    __syncthreads();

    // -------- phase B1: reduce over warps (512 entries, 2 per thread) ---
#pragma unroll
    for (int e = tid; e < SIM_ROWS * 16; e += 256) {
        int r = e >> 4, vv = e & 15;
        float s = 0.f;
#pragma unroll
        for (int w = 0; w < 8; w++) s += stage[r][w][vv];
        tot[r][vv] = s;
    }
    __syncthreads();

    // -------- phase B2: finalize, one thread per row --------
    if (tid < SIM_ROWS) {
        int r = tid;
        float fin = 1.f / fmaxf(sqrtf(tot[r][15]), 1e-12f);
        float best = -1e30f; int bi = 0; float sum = 0.f;
#pragma unroll
        for (int k = 0; k < KC; k++) {
            float sim = tot[r][k] * fin * s_cn[k];
            sum += sim;
            if (sim > best) { best = sim; bi = k; }
        }
        g_avg[mod][row0 + r] = sum * (1.0f / KC);
        g_assign[mod][row0 + r] = bi;
        atomicAdd(&g_counts_i[mod][bi], 1);
    }
}

// ---------------- node 4: radix select + attractive loss ----------------
__global__ void select_attr_kernel(int rank0) {
    int mod = blockIdx.x;
    const float* avg = g_avg[mod];
    __shared__ unsigned int hist[256];
    __shared__ unsigned int sc[256];
    __shared__ unsigned int s_prefix;
    __shared__ int s_rank;
    __shared__ float s_thr;
    int tid = threadIdx.x;
    if (tid == 0) { s_prefix = 0u; s_rank = rank0; }
    __syncthreads();

    for (int p = 3; p >= 0; p--) {
        hist[tid] = 0u;
        __syncthreads();
        unsigned int mask = (p == 3) ? 0u : (0xFFFFFFFFu << ((p + 1) * 8));
        unsigned int pref = s_prefix;
        int r = s_rank;
        for (int i = tid; i < B; i += 256) {
            unsigned int u = __float_as_uint(avg[i]);
            u = (u & 0x80000000u) ? ~u : (u | 0x80000000u);
            if ((u & mask) == (pref & mask))
                atomicAdd(&hist[(u >> (p * 8)) & 255u], 1u);
        }
        __syncthreads();
        // parallel inclusive scan over 256 bins
        sc[tid] = hist[tid];
        __syncthreads();
#pragma unroll
        for (int off = 1; off < 256; off <<= 1) {
            unsigned int add = (tid >= off) ? sc[tid - off] : 0u;
            __syncthreads();
            sc[tid] += add;
            __syncthreads();
        }
        unsigned int inc = sc[tid], exc = inc - hist[tid];
        if ((unsigned int)r >= exc && (unsigned int)r < inc) {
            s_prefix = pref | ((unsigned int)tid << (p * 8));
            s_rank = r - (int)exc;
        }
        __syncthreads();
    }
    if (tid == 0) {
        unsigned int u = s_prefix;
        unsigned int bits = (u & 0x80000000u) ? (u ^ 0x80000000u) : ~u;
        s_thr = __uint_as_float(bits);
    }
    __syncthreads();

    float thr = s_thr;
    float s = 0.f;
    for (int i = tid; i < B; i += 256) {
        float a = avg[i];
        float w = 1.f / (1.f + expf(-5.0f * (a - thr)));   // ALPHA = 5
        s += w * (1.f - a);
    }
    __shared__ float sm[256];
    sm[tid] = s; __syncthreads();
    for (int o = 128; o > 0; o >>= 1) {
        if (tid < o) sm[tid] += sm[tid + o];
        __syncthreads();
    }
    if (tid == 0) atomicAdd(&g_attr, sm[0]);
}

// ---------------- node 5: segment sums of softmax probs ----------------
#define SEG_ROWS 256
__global__ __launch_bounds__(256) void seg_kernel(const float* __restrict__ outp) {
    __shared__ float acc[NMOD * KC * 256];   // 46080 B
    int tid = threadIdx.x;
    int c = blockIdx.x * 256 + tid;
    bool valid = c < C;
    for (int j = tid; j < NMOD * KC * 256; j += 256) acc[j] = 0.f;
    __syncthreads();

    int r0 = blockIdx.y * SEG_ROWS;
    for (int rr = 0; rr < SEG_ROWS; rr++) {
        int r = r0 + rr;
        int a0 = __ldg(&g_assign[0][r]), a1 = __ldg(&g_assign[1][r]), a2 = __ldg(&g_assign[2][r]);
        float rm = __ldg(&g_rmax[r]);
        float ri = 1.f / __ldg(&g_rsum[r]);
        if (valid) {
            float p = __expf(outp[(size_t)r * C + c] - rm) * ri;
            acc[a0 * 256 + tid]            += p;
            acc[(KC + a1) * 256 + tid]     += p;
            acc[(2 * KC + a2) * 256 + tid] += p;
        }
    }
    __syncthreads();
    if (valid) {
#pragma unroll
        for (int j = 0; j < NMOD * KC; j++)
            atomicAdd(&((float*)g_segsum)[(size_t)j * C + c], acc[j * 256 + tid]);
    }
}

// ---------------- node 6: gated entropy + finalize (ticket) ----------------
__global__ void entropy_final_kernel(float* dout_last) {
    int bk = blockIdx.x;  // 0..44
    float cnt = (float)((int*)g_counts_i)[bk];
    float inv = 1.f / fmaxf(cnt, 1.f);
    const float* sums = ((float*)g_segsum) + (size_t)bk * C;
    float s = 0.f;
    for (int i = threadIdx.x; i < C; i += 256) {
        float mp = sums[i] * inv;
        s += mp * logf(mp + 1e-8f);
    }
    __shared__ float sm[256];
    sm[threadIdx.x] = s; __syncthreads();
    for (int o = 128; o > 0; o >>= 1) {
        if (threadIdx.x < o) sm[threadIdx.x] += sm[threadIdx.x + o];
        __syncthreads();
    }
    if (threadIdx.x == 0) {
        if (cnt >= 3.0f) atomicAdd(&g_div, sm[0]);
        __threadfence();
        int t = atomicAdd(&g_ticket, 1);
        if (t == NMOD * KC - 1) {
            float attr = atomicAdd(&g_attr, 0.f);
            float div  = atomicAdd(&g_div, 0.f);
            // LAM_CLUSTER = 6.0, LAM_DIV = 0.1
            *dout_last = 6.0f * (attr / (float)B) + 0.1f * div;
        }
    }
}

// ---------------- launch ----------------
extern "C" void kernel_launch(void* const* d_in, const int* in_sizes, int n_in,
                              void* d_out, int out_size) {
    const float* f0 = (const float*)d_in[0];
    const float* f1 = (const float*)d_in[1];
    const float* f2 = (const float*)d_in[2];
    const float* c0 = (const float*)d_in[3];
    const float* c1 = (const float*)d_in[4];
    const float* c2 = (const float*)d_in[5];
    const float* outp = (const float*)d_in[6];
    float* dout = (float*)d_out;
    (void)n_in; (void)in_sizes;

    cnorm_init_kernel<<<NMOD * KC, 256>>>(c0, c1, c2);
    softmax_kernel<<<B / 8, 256>>>(outp, dout);
    sim_kernel<<<dim3(B / SIM_ROWS, NMOD), 256>>>(f0, f1, f2, c0, c1, c2);

    int rank0 = B - (int)((double)B * 0.6);   // = 6554 = int(n*PCT) complement
    select_attr_kernel<<<NMOD, 256>>>(rank0);
    seg_kernel<<<dim3((C + 255) / 256, B / SEG_ROWS), 256>>>(outp);
    entropy_final_kernel<<<NMOD * KC, 256>>>(dout + (size_t)out_size - 1);
}

// round 4
// speedup vs baseline: 1.1623x; 1.0379x over previous
#include <cuda_runtime.h>
#include <math.h>

#define B    16384
#define D    1024
#define KC   15
#define C    1000
#define NMOD 3

// ---------------- scratch (device globals; no allocation) ----------------
__device__ float g_cnorm[NMOD][KC];
__device__ float g_avg[NMOD][B];
__device__ int   g_assign[NMOD][B];
__device__ int   g_counts_i[NMOD][KC];
__device__ float g_rmax[B];
__device__ float g_rsum[B];
__device__ float g_segsum[NMOD][KC][C];
__device__ float g_attr;
__device__ float g_div;

// ---------------- node 1: centroid norms + zero accumulators --------------
__global__ void cnorm_init_kernel(const float* __restrict__ c0,
                                  const float* __restrict__ c1,
                                  const float* __restrict__ c2) {
    int b = blockIdx.x;           // 0..44
    int mod = b / KC, k = b % KC;
    float* seg = ((float*)g_segsum) + (size_t)b * C;
    for (int i = threadIdx.x; i < C; i += 256) seg[i] = 0.f;
    if (b == 0) {
        if (threadIdx.x == 0) { g_attr = 0.f; g_div = 0.f; }
        if (threadIdx.x < NMOD * KC) ((int*)g_counts_i)[threadIdx.x] = 0;
    }
    const float* cen = mod == 0 ? c0 : (mod == 1 ? c1 : c2);
    const float4* row = (const float4*)(cen + (size_t)k * D);
    float s = 0.f;
    for (int i = threadIdx.x; i < D / 4; i += 256) {
        float4 v = row[i];
        s += v.x * v.x + v.y * v.y + v.z * v.z + v.w * v.w;
    }
    __shared__ float sm[256];
    sm[threadIdx.x] = s; __syncthreads();
    for (int o = 128; o > 0; o >>= 1) {
        if (threadIdx.x < o) sm[threadIdx.x] += sm[threadIdx.x + o];
        __syncthreads();
    }
    if (threadIdx.x == 0)
        g_cnorm[mod][k] = 1.f / fmaxf(sqrtf(sm[0]), 1e-12f);
}

// ---------------- nodes 2+3: softmax stats + copy (half grid each) --------
__global__ __launch_bounds__(256) void softmax_kernel(const float* __restrict__ outp,
                                                      float* __restrict__ ocopy,
                                                      int row_base) {
    int warp = threadIdx.x >> 5, lane = threadIdx.x & 31;
    int row = row_base + blockIdx.x * 8 + warp;
    const float4* r4 = (const float4*)(outp + (size_t)row * C);
    float4* w4 = (float4*)(ocopy + (size_t)row * C);
    float4 a[8];
    float m = -INFINITY;
#pragma unroll
    for (int i = 0; i < 8; i++) {
        int j = lane + i * 32;
        if (j < C / 4) {
            float4 x = r4[j]; a[i] = x; w4[j] = x;
            m = fmaxf(m, fmaxf(fmaxf(x.x, x.y), fmaxf(x.z, x.w)));
        }
    }
#pragma unroll
    for (int o = 16; o > 0; o >>= 1) m = fmaxf(m, __shfl_xor_sync(0xffffffffu, m, o));
    float s = 0.f;
#pragma unroll
    for (int i = 0; i < 8; i++) {
        int j = lane + i * 32;
        if (j < C / 4)
            s += __expf(a[i].x - m) + __expf(a[i].y - m) + __expf(a[i].z - m) + __expf(a[i].w - m);
    }
#pragma unroll
    for (int o = 16; o > 0; o >>= 1) s += __shfl_xor_sync(0xffffffffu, s, o);
    if (lane == 0) { g_rmax[row] = m; g_rsum[row] = s; }
}

// ---------------- node 4: similarities (scalar FMA, phase A/B) ------------
#define SIM_ROWS 32
__global__ __launch_bounds__(256, 2) void sim_kernel(
    const float* __restrict__ f0, const float* __restrict__ f1, const float* __restrict__ f2,
    const float* __restrict__ c0, const float* __restrict__ c1, const float* __restrict__ c2) {
    int mod = blockIdx.y;
    const float* fea = mod == 0 ? f0 : (mod == 1 ? f1 : f2);
    const float* cen = mod == 0 ? c0 : (mod == 1 ? c1 : c2);
    int tid = threadIdx.x;
    int lane = tid & 31, warp = tid >> 5;
    int col = tid * 4;

    float4 cw[KC];
#pragma unroll
    for (int k = 0; k < KC; k++)
        cw[k] = *(const float4*)(cen + (size_t)k * D + col);

    __shared__ float stage[SIM_ROWS][8][16];   // 16 KB
    __shared__ float tot[SIM_ROWS][16];        // 2 KB
    __shared__ float s_cn[KC];
    if (tid < KC) s_cn[tid] = g_cnorm[mod][tid];

    // value index held by this lane after the butterfly: bit-reversed nibble
    int vidx = ((lane & 1) ? 8 : 0) | ((lane & 2) ? 4 : 0) |
               ((lane & 4) ? 2 : 0) | ((lane & 8) ? 1 : 0);

    int row0 = blockIdx.x * SIM_ROWS;
    const float4* fp = (const float4*)(fea + (size_t)row0 * D) + tid;
    float4 f = fp[0];

    // -------- phase A: butterfly partials for 32 rows, no syncs --------
    for (int rr = 0; rr < SIM_ROWS; rr++) {
        float4 fn;
        if (rr + 1 < SIM_ROWS) fn = fp[(rr + 1) * (D / 4)];

        float v[16];
        v[15] = f.x * f.x + f.y * f.y + f.z * f.z + f.w * f.w;
#pragma unroll
        for (int k = 0; k < KC; k++)
            v[k] = f.x * cw[k].x + f.y * cw[k].y + f.z * cw[k].z + f.w * cw[k].w;

        // multi-value warp reduction: 16 values across 32 lanes
#pragma unroll
        for (int s = 0; s < 4; s++) {
            int d2 = 1 << s;
            int half = 8 >> s;
            bool hi = (lane & d2) != 0;
#pragma unroll
            for (int i = 0; i < half; i++) {
                float send = hi ? v[i] : v[i + half];
                float recv = __shfl_xor_sync(0xffffffffu, send, d2);
                v[i] = (hi ? v[i + half] : v[i]) + recv;
            }
        }
        v[0] += __shfl_xor_sync(0xffffffffu, v[0], 16);

        if (lane < 16) stage[rr][warp][vidx] = v[0];
        f = fn;
    }
    __syncthreads();

    // -------- phase B1: reduce over warps --------
#pragma unroll
    for (int e = tid; e < SIM_ROWS * 16; e += 256) {
        int r = e >> 4, vv = e & 15;
        float s = 0.f;
#pragma unroll
        for (int w = 0; w < 8; w++) s += stage[r][w][vv];
        tot[r][vv] = s;
    }
    __syncthreads();

    // -------- phase B2: finalize, one thread per row --------
    if (tid < SIM_ROWS) {
        int r = tid;
        float fin = 1.f / fmaxf(sqrtf(tot[r][15]), 1e-12f);
        float best = -1e30f; int bi = 0; float sum = 0.f;
#pragma unroll
        for (int k = 0; k < KC; k++) {
            float sim = tot[r][k] * fin * s_cn[k];
            sum += sim;
            if (sim > best) { best = sim; bi = k; }
        }
        g_avg[mod][row0 + r] = sum * (1.0f / KC);
        g_assign[mod][row0 + r] = bi;
        atomicAdd(&g_counts_i[mod][bi], 1);
    }
}

// ---------------- node 5: radix select + attractive (smem-resident) -------
// one block of 1024 threads per modality; all 16384 keys cached in 64KB
// dynamic smem; 4 radix passes + attractive sum never touch DRAM again.
__global__ __launch_bounds__(1024) void select_attr_kernel(int rank0) {
    extern __shared__ unsigned int skeys[];       // 16384 u32 = 64 KB
    __shared__ unsigned int hist[256];
    __shared__ unsigned int sc[256];
    __shared__ unsigned int s_prefix;
    __shared__ int s_rank;
    __shared__ float s_thr;
    __shared__ float sred[32];

    int mod = blockIdx.x;
    const float* avg = g_avg[mod];
    int tid = threadIdx.x;
    int lane = tid & 31, warp = tid >> 5;

    // load + order-preserving transform
#pragma unroll
    for (int i = tid; i < B; i += 1024) {
        unsigned int u = __float_as_uint(avg[i]);
        skeys[i] = (u & 0x80000000u) ? ~u : (u | 0x80000000u);
    }
    if (tid == 0) { s_prefix = 0u; s_rank = rank0; }
    __syncthreads();

    for (int p = 3; p >= 0; p--) {
        if (tid < 256) hist[tid] = 0u;
        __syncthreads();
        unsigned int mask = (p == 3) ? 0u : (0xFFFFFFFFu << ((p + 1) * 8));
        unsigned int pref = s_prefix;
        int r = s_rank;
#pragma unroll
        for (int i = tid; i < B; i += 1024) {
            unsigned int u = skeys[i];
            if ((u & mask) == (pref & mask))
                atomicAdd(&hist[(u >> (p * 8)) & 255u], 1u);
        }
        __syncthreads();
        // inclusive scan of 256 bins (first 256 threads)
        if (tid < 256) sc[tid] = hist[tid];
        __syncthreads();
#pragma unroll
        for (int off = 1; off < 256; off <<= 1) {
            unsigned int add = 0u;
            if (tid < 256 && tid >= off) add = sc[tid - off];
            __syncthreads();
            if (tid < 256) sc[tid] += add;
            __syncthreads();
        }
        if (tid < 256) {
            unsigned int inc = sc[tid], exc = inc - hist[tid];
            if ((unsigned int)r >= exc && (unsigned int)r < inc) {
                s_prefix = pref | ((unsigned int)tid << (p * 8));
                s_rank = r - (int)exc;
            }
        }
        __syncthreads();
    }
    if (tid == 0) {
        unsigned int u = s_prefix;
        unsigned int bits = (u & 0x80000000u) ? (u ^ 0x80000000u) : ~u;
        s_thr = __uint_as_float(bits);
    }
    __syncthreads();

    float thr = s_thr;
    float s = 0.f;
#pragma unroll
    for (int i = tid; i < B; i += 1024) {
        unsigned int u = skeys[i];
        unsigned int bits = (u & 0x80000000u) ? (u ^ 0x80000000u) : ~u;
        float a = __uint_as_float(bits);
        float w = 1.f / (1.f + expf(-5.0f * (a - thr)));   // ALPHA = 5
        s += w * (1.f - a);
    }
#pragma unroll
    for (int o = 16; o > 0; o >>= 1) s += __shfl_xor_sync(0xffffffffu, s, o);
    if (lane == 0) sred[warp] = s;
    __syncthreads();
    if (tid < 32) {
        float t = sred[tid];
#pragma unroll
        for (int o = 16; o > 0; o >>= 1) t += __shfl_xor_sync(0xffffffffu, t, o);
        if (tid == 0) atomicAdd(&g_attr, t);
    }
}

// ---------------- node 6: segment sums of softmax probs ----------------
#define SEG_ROWS 128
__global__ __launch_bounds__(256) void seg_kernel(const float* __restrict__ outp) {
    __shared__ float acc[NMOD * KC * 256];   // 46080 B
    int tid = threadIdx.x;
    int c = blockIdx.x * 256 + tid;
    bool valid = c < C;
    for (int j = tid; j < NMOD * KC * 256; j += 256) acc[j] = 0.f;
    __syncthreads();

    int r0 = blockIdx.y * SEG_ROWS;
    for (int rr = 0; rr < SEG_ROWS; rr++) {
        int r = r0 + rr;
        int a0 = __ldg(&g_assign[0][r]), a1 = __ldg(&g_assign[1][r]), a2 = __ldg(&g_assign[2][r]);
        float rm = __ldg(&g_rmax[r]);
        float ri = 1.f / __ldg(&g_rsum[r]);
        if (valid) {
            float p = __expf(outp[(size_t)r * C + c] - rm) * ri;
            acc[a0 * 256 + tid]            += p;
            acc[(KC + a1) * 256 + tid]     += p;
            acc[(2 * KC + a2) * 256 + tid] += p;
        }
    }
    __syncthreads();
    if (valid) {
#pragma unroll
        for (int j = 0; j < NMOD * KC; j++)
            atomicAdd(&((float*)g_segsum)[(size_t)j * C + c], acc[j * 256 + tid]);
    }
}

// ---------------- node 7: gated entropy + finalize ----------------
__global__ void entropy_final_kernel(float* dout_last) {
    __shared__ float s_part[NMOD * KC];   // per-cluster gated entropies
    int tid = threadIdx.x;                // one block, 256 threads
    // each of the 45 clusters reduced by a "sub-block" of threads via loop
    for (int bk = 0; bk < NMOD * KC; bk++) {
        float cnt = (float)((int*)g_counts_i)[bk];
        float inv = 1.f / fmaxf(cnt, 1.f);
        const float* sums = ((float*)g_segsum) + (size_t)bk * C;
        float s = 0.f;
        for (int i = tid; i < C; i += 256) {
            float mp = sums[i] * inv;
            s += mp * logf(mp + 1e-8f);
        }
        __shared__ float sm[256];
        sm[tid] = s; __syncthreads();
        for (int o = 128; o > 0; o >>= 1) {
            if (tid < o) sm[tid] += sm[tid + o];
            __syncthreads();
        }
        if (tid == 0) s_part[bk] = (cnt >= 3.0f) ? sm[0] : 0.f;
        __syncthreads();
    }
    if (tid == 0) {
        float div = 0.f;
#pragma unroll
        for (int bk = 0; bk < NMOD * KC; bk++) div += s_part[bk];
        // LAM_CLUSTER = 6.0, LAM_DIV = 0.1
        *dout_last = 6.0f * (g_attr / (float)B) + 0.1f * div;
    }
}

// ---------------- launch ----------------
extern "C" void kernel_launch(void* const* d_in, const int* in_sizes, int n_in,
                              void* d_out, int out_size) {
    const float* f0 = (const float*)d_in[0];
    const float* f1 = (const float*)d_in[1];
    const float* f2 = (const float*)d_in[2];
    const float* c0 = (const float*)d_in[3];
    const float* c1 = (const float*)d_in[4];
    const float* c2 = (const float*)d_in[5];
    const float* outp = (const float*)d_in[6];
    float* dout = (float*)d_out;
    (void)n_in; (void)in_sizes;

    // opt-in to 64KB dynamic smem for the select kernel (idempotent, capture-legal)
    cudaFuncSetAttribute(select_attr_kernel,
                         cudaFuncAttributeMaxDynamicSharedMemorySize, B * 4);

    cnorm_init_kernel<<<NMOD * KC, 256>>>(c0, c1, c2);                     // #1
    softmax_kernel<<<B / 16, 256>>>(outp, dout, 0);                        // #2
    softmax_kernel<<<B / 16, 256>>>(outp, dout, B / 2);                    // #3
    sim_kernel<<<dim3(B / SIM_ROWS, NMOD), 256>>>(f0, f1, f2, c0, c1, c2); // #4 (profiled slot)

    int rank0 = B - (int)((double)B * 0.6);   // = 6554
    select_attr_kernel<<<NMOD, 1024, B * 4>>>(rank0);                      // #5
    seg_kernel<<<dim3((C + 255) / 256, B / SEG_ROWS), 256>>>(outp);        // #6
    entropy_final_kernel<<<1, 256>>>(dout + (size_t)out_size - 1);         // #7
}

// round 6
// speedup vs baseline: 1.3330x; 1.1469x over previous
#include <cuda_runtime.h>
#include <math.h>

#define B    16384
#define D    1024
#define KC   15
#define C    1000
#define NMOD 3

// ---------------- scratch (device globals; no allocation) ----------------
#define SEG_BY   74
#define SEG_ROWS 222   // 74*222 = 16428 >= B
#define CPAD     1024

__device__ float g_cnorm[NMOD][KC];
__device__ float g_avg[NMOD][B];
__device__ int   g_assign[NMOD][B];
__device__ int   g_counts_i[NMOD][KC];
__device__ float g_rmax[B];
__device__ float g_rinv[B];                    // 1/rowsum (division hoisted)
__device__ float g_part[SEG_BY][NMOD * KC][CPAD];  // per-block partial seg sums
__device__ float g_entpart[NMOD * KC];
__device__ float g_attr;

// ---------------- node 1: centroid norms + zero small accumulators --------
__global__ void cnorm_init_kernel(const float* __restrict__ c0,
                                  const float* __restrict__ c1,
                                  const float* __restrict__ c2) {
    int b = blockIdx.x;           // 0..44
    int mod = b / KC, k = b % KC;
    if (b == 0) {
        if (threadIdx.x == 0) g_attr = 0.f;
        if (threadIdx.x < NMOD * KC) ((int*)g_counts_i)[threadIdx.x] = 0;
    }
    const float* cen = mod == 0 ? c0 : (mod == 1 ? c1 : c2);
    const float4* row = (const float4*)(cen + (size_t)k * D);
    float s = 0.f;
    for (int i = threadIdx.x; i < D / 4; i += 256) {
        float4 v = row[i];
        s += v.x * v.x + v.y * v.y + v.z * v.z + v.w * v.w;
    }
    __shared__ float sm[256];
    sm[threadIdx.x] = s; __syncthreads();
    for (int o = 128; o > 0; o >>= 1) {
        if (threadIdx.x < o) sm[threadIdx.x] += sm[threadIdx.x + o];
        __syncthreads();
    }
    if (threadIdx.x == 0)
        g_cnorm[mod][k] = 1.f / fmaxf(sqrtf(sm[0]), 1e-12f);
}

// ---------------- node 2: softmax stats + copy (float4, stores 1/sum) -----
__global__ __launch_bounds__(256) void softmax_kernel(const float* __restrict__ outp,
                                                      float* __restrict__ ocopy) {
    int warp = threadIdx.x >> 5, lane = threadIdx.x & 31;
    int row = blockIdx.x * 8 + warp;
    const float4* r4 = (const float4*)(outp + (size_t)row * C);
    float4* w4 = (float4*)(ocopy + (size_t)row * C);
    float4 a[8];
    float m = -INFINITY;
#pragma unroll
    for (int i = 0; i < 8; i++) {
        int j = lane + i * 32;
        if (j < C / 4) {
            float4 x = r4[j]; a[i] = x; w4[j] = x;
            m = fmaxf(m, fmaxf(fmaxf(x.x, x.y), fmaxf(x.z, x.w)));
        }
    }
#pragma unroll
    for (int o = 16; o > 0; o >>= 1) m = fmaxf(m, __shfl_xor_sync(0xffffffffu, m, o));
    float s = 0.f;
#pragma unroll
    for (int i = 0; i < 8; i++) {
        int j = lane + i * 32;
        if (j < C / 4)
            s += __expf(a[i].x - m) + __expf(a[i].y - m) + __expf(a[i].z - m) + __expf(a[i].w - m);
    }
#pragma unroll
    for (int o = 16; o > 0; o >>= 1) s += __shfl_xor_sync(0xffffffffu, s, o);
    if (lane == 0) { g_rmax[row] = m; g_rinv[row] = 1.f / s; }
}

// ---------------- node 3: similarities (butterfly, known-good) ------------
#define SIM_ROWS 32
__global__ __launch_bounds__(256, 2) void sim_kernel(
    const float* __restrict__ f0, const float* __restrict__ f1, const float* __restrict__ f2,
    const float* __restrict__ c0, const float* __restrict__ c1, const float* __restrict__ c2) {
    int mod = blockIdx.y;
    const float* fea = mod == 0 ? f0 : (mod == 1 ? f1 : f2);
    const float* cen = mod == 0 ? c0 : (mod == 1 ? c1 : c2);
    int tid = threadIdx.x;
    int lane = tid & 31, warp = tid >> 5;
    int col = tid * 4;

    float4 cw[KC];
#pragma unroll
    for (int k = 0; k < KC; k++)
        cw[k] = *(const float4*)(cen + (size_t)k * D + col);

    __shared__ float stage[SIM_ROWS][8][16];   // 16 KB
    __shared__ float tot[SIM_ROWS][16];        // 2 KB
    __shared__ float s_cn[KC];
    if (tid < KC) s_cn[tid] = g_cnorm[mod][tid];

    int vidx = ((lane & 1) ? 8 : 0) | ((lane & 2) ? 4 : 0) |
               ((lane & 4) ? 2 : 0) | ((lane & 8) ? 1 : 0);

    int row0 = blockIdx.x * SIM_ROWS;
    const float4* fp = (const float4*)(fea + (size_t)row0 * D) + tid;
    float4 f = fp[0];

    for (int rr = 0; rr < SIM_ROWS; rr++) {
        float4 fn;
        if (rr + 1 < SIM_ROWS) fn = fp[(rr + 1) * (D / 4)];

        float v[16];
        v[15] = f.x * f.x + f.y * f.y + f.z * f.z + f.w * f.w;
#pragma unroll
        for (int k = 0; k < KC; k++)
            v[k] = f.x * cw[k].x + f.y * cw[k].y + f.z * cw[k].z + f.w * cw[k].w;

#pragma unroll
        for (int s = 0; s < 4; s++) {
            int d2 = 1 << s;
            int half = 8 >> s;
            bool hi = (lane & d2) != 0;
#pragma unroll
            for (int i = 0; i < half; i++) {
                float send = hi ? v[i] : v[i + half];
                float recv = __shfl_xor_sync(0xffffffffu, send, d2);
                v[i] = (hi ? v[i + half] : v[i]) + recv;
            }
        }
        v[0] += __shfl_xor_sync(0xffffffffu, v[0], 16);

        if (lane < 16) stage[rr][warp][vidx] = v[0];
        f = fn;
    }
    __syncthreads();

#pragma unroll
    for (int e = tid; e < SIM_ROWS * 16; e += 256) {
        int r = e >> 4, vv = e & 15;
        float s = 0.f;
#pragma unroll
        for (int w = 0; w < 8; w++) s += stage[r][w][vv];
        tot[r][vv] = s;
    }
    __syncthreads();

    if (tid < SIM_ROWS) {
        int r = tid;
        float fin = 1.f / fmaxf(sqrtf(tot[r][15]), 1e-12f);
        float best = -1e30f; int bi = 0; float sum = 0.f;
#pragma unroll
        for (int k = 0; k < KC; k++) {
            float sim = tot[r][k] * fin * s_cn[k];
            sum += sim;
            if (sim > best) { best = sim; bi = k; }
        }
        g_avg[mod][row0 + r] = sum * (1.0f / KC);
        g_assign[mod][row0 + r] = bi;
        atomicAdd(&g_counts_i[mod][bi], 1);
    }
}

// ---------------- node 4 (PROFILED): segment partial sums -----------------
// grid (4, SEG_BY); 2 blocks/SM. Per-row uniforms staged in smem per chunk;
// no divisions, no global atomics (plain partial stores to g_part).
#define SEG_CHUNK 64
__global__ __launch_bounds__(256) void seg_kernel(const float* __restrict__ outp) {
    __shared__ float acc[NMOD * KC * 256];   // 46080 B
    __shared__ int   s_a[3][SEG_CHUNK];
    __shared__ float s_rm[SEG_CHUNK];
    __shared__ float s_ri[SEG_CHUNK];
    int tid = threadIdx.x;
    int c = blockIdx.x * 256 + tid;
    bool valid = c < C;
    for (int j = tid; j < NMOD * KC * 256; j += 256) acc[j] = 0.f;

    int r0 = blockIdx.y * SEG_ROWS;
    int rend = r0 + SEG_ROWS; if (rend > B) rend = B;

    for (int cb = r0; cb < rend; cb += SEG_CHUNK) {
        int clen = rend - cb; if (clen > SEG_CHUNK) clen = SEG_CHUNK;
        __syncthreads();
        // cooperative staging of per-row uniforms
        if (tid < clen) {
            s_a[0][tid] = g_assign[0][cb + tid];
            s_a[1][tid] = g_assign[1][cb + tid];
            s_a[2][tid] = g_assign[2][cb + tid];
            s_rm[tid]   = g_rmax[cb + tid];
            s_ri[tid]   = g_rinv[cb + tid];
        }
        __syncthreads();
        if (valid) {
            const float* op = outp + (size_t)cb * C + c;
            for (int rr = 0; rr < clen; rr++) {
                float p = __expf(op[(size_t)rr * C] - s_rm[rr]) * s_ri[rr];
                acc[s_a[0][rr] * 256 + tid]            += p;
                acc[(KC + s_a[1][rr]) * 256 + tid]     += p;
                acc[(2 * KC + s_a[2][rr]) * 256 + tid] += p;
            }
        }
    }
    __syncthreads();
    if (valid) {
        float* dst = &g_part[blockIdx.y][0][c];
#pragma unroll
        for (int j = 0; j < NMOD * KC; j++)
            dst[(size_t)j * CPAD] = acc[j * 256 + tid];
    }
}

// ---------------- node 5: radix select + attractive (smem-resident) -------
__global__ __launch_bounds__(1024) void select_attr_kernel(int rank0) {
    extern __shared__ unsigned int skeys[];       // 16384 u32 = 64 KB
    __shared__ unsigned int hist[256];
    __shared__ unsigned int sc[256];
    __shared__ unsigned int s_prefix;
    __shared__ int s_rank;
    __shared__ float s_thr;
    __shared__ float sred[32];

    int mod = blockIdx.x;
    const float* avg = g_avg[mod];
    int tid = threadIdx.x;
    int lane = tid & 31, warp = tid >> 5;

#pragma unroll
    for (int i = tid; i < B; i += 1024) {
        unsigned int u = __float_as_uint(avg[i]);
        skeys[i] = (u & 0x80000000u) ? ~u : (u | 0x80000000u);
    }
    if (tid == 0) { s_prefix = 0u; s_rank = rank0; }
    __syncthreads();

    for (int p = 3; p >= 0; p--) {
        if (tid < 256) hist[tid] = 0u;
        __syncthreads();
        unsigned int mask = (p == 3) ? 0u : (0xFFFFFFFFu << ((p + 1) * 8));
        unsigned int pref = s_prefix;
        int r = s_rank;
#pragma unroll
        for (int i = tid; i < B; i += 1024) {
            unsigned int u = skeys[i];
            if ((u & mask) == (pref & mask))
                atomicAdd(&hist[(u >> (p * 8)) & 255u], 1u);
        }
        __syncthreads();
        if (tid < 256) sc[tid] = hist[tid];
        __syncthreads();
#pragma unroll
        for (int off = 1; off < 256; off <<= 1) {
            unsigned int add = 0u;
            if (tid < 256 && tid >= off) add = sc[tid - off];
            __syncthreads();
            if (tid < 256) sc[tid] += add;
            __syncthreads();
        }
        if (tid < 256) {
            unsigned int inc = sc[tid], exc = inc - hist[tid];
            if ((unsigned int)r >= exc && (unsigned int)r < inc) {
                s_prefix = pref | ((unsigned int)tid << (p * 8));
                s_rank = r - (int)exc;
            }
        }
        __syncthreads();
    }
    if (tid == 0) {
        unsigned int u = s_prefix;
        unsigned int bits = (u & 0x80000000u) ? (u ^ 0x80000000u) : ~u;
        s_thr = __uint_as_float(bits);
    }
    __syncthreads();

    float thr = s_thr;
    float s = 0.f;
#pragma unroll
    for (int i = tid; i < B; i += 1024) {
        unsigned int u = skeys[i];
        unsigned int bits = (u & 0x80000000u) ? (u ^ 0x80000000u) : ~u;
        float a = __uint_as_float(bits);
        float w = 1.f / (1.f + expf(-5.0f * (a - thr)));   // ALPHA = 5
        s += w * (1.f - a);
    }
#pragma unroll
    for (int o = 16; o > 0; o >>= 1) s += __shfl_xor_sync(0xffffffffu, s, o);
    if (lane == 0) sred[warp] = s;
    __syncthreads();
    if (tid < 32) {
        float t = sred[tid];
#pragma unroll
        for (int o = 16; o > 0; o >>= 1) t += __shfl_xor_sync(0xffffffffu, t, o);
        if (tid == 0) atomicAdd(&g_attr, t);
    }
}

// ---------------- node 6: gated entropy over summed partials --------------
__global__ void entropy_kernel() {
    int bk = blockIdx.x;  // 0..44
    float cnt = (float)((int*)g_counts_i)[bk];
    float inv = 1.f / fmaxf(cnt, 1.f);
    float s = 0.f;
    for (int i = threadIdx.x; i < C; i += 256) {
        float t = 0.f;
#pragma unroll 2
        for (int by = 0; by < SEG_BY; by++) t += g_part[by][bk][i];
        float mp = t * inv;
        s += mp * __logf(mp + 1e-8f);
    }
    __shared__ float sm[256];
    sm[threadIdx.x] = s; __syncthreads();
    for (int o = 128; o > 0; o >>= 1) {
        if (threadIdx.x < o) sm[threadIdx.x] += sm[threadIdx.x + o];
        __syncthreads();
    }
    if (threadIdx.x == 0) g_entpart[bk] = (cnt >= 3.0f) ? sm[0] : 0.f;
}

// ---------------- node 7: finalize ----------------
__global__ void finalize_kernel(float* dout_last) {
    int lane = threadIdx.x;   // 64 threads
    float s = (lane < NMOD * KC) ? g_entpart[lane] : 0.f;
#pragma unroll
    for (int o = 16; o > 0; o >>= 1) s += __shfl_xor_sync(0xffffffffu, s, o);
    __shared__ float w0, w1;
    if (lane == 0) w0 = s;
    if (lane == 32) w1 = s;
    __syncthreads();
    if (lane == 0) {
        // LAM_CLUSTER = 6.0, LAM_DIV = 0.1
        *dout_last = 6.0f * (g_attr / (float)B) + 0.1f * (w0 + w1);
    }
}

// ---------------- launch ----------------
extern "C" void kernel_launch(void* const* d_in, const int* in_sizes, int n_in,
                              void* d_out, int out_size) {
    const float* f0 = (const float*)d_in[0];
    const float* f1 = (const float*)d_in[1];
    const float* f2 = (const float*)d_in[2];
    const float* c0 = (const float*)d_in[3];
    const float* c1 = (const float*)d_in[4];
    const float* c2 = (const float*)d_in[5];
    const float* outp = (const float*)d_in[6];
    float* dout = (float*)d_out;
    (void)n_in; (void)in_sizes;

    cudaFuncSetAttribute(select_attr_kernel,
                         cudaFuncAttributeMaxDynamicSharedMemorySize, B * 4);

    cnorm_init_kernel<<<NMOD * KC, 256>>>(c0, c1, c2);                     // #1
    softmax_kernel<<<B / 8, 256>>>(outp, dout);                            // #2
    sim_kernel<<<dim3(B / SIM_ROWS, NMOD), 256>>>(f0, f1, f2, c0, c1, c2); // #3

    seg_kernel<<<dim3(4, SEG_BY), 256>>>(outp);                            // #4 (profiled)

    int rank0 = B - (int)((double)B * 0.6);   // = 6554
    select_attr_kernel<<<NMOD, 1024, B * 4>>>(rank0);                      // #5
    entropy_kernel<<<NMOD * KC, 256>>>();                                  // #6
    finalize_kernel<<<1, 64>>>(dout + (size_t)out_size - 1);               // #7
}

// round 7
// speedup vs baseline: 1.5148x; 1.1364x over previous
#include <cuda_runtime.h>
#include <math.h>

#define B    16384
#define D    1024
#define KC   15
#define C    1000
#define NMOD 3

#define SEG_BY   74
#define SEG_ROWS 224   // 74*224 = 16576 >= B, all chunks multiple of 8
#define CPAD     1024

// ---------------- scratch (device globals; no allocation) ----------------
__device__ float g_avg[NMOD][B];
__device__ int   g_assign[NMOD][B];
__device__ float g_rmax[B];
__device__ float g_rinv[B];
__device__ float g_part[NMOD * KC][SEG_BY][CPAD];  // transposed: entropy reads contiguous
__device__ float g_entpart[NMOD * KC];
__device__ float g_attrpart[NMOD];

// ---------------- softmax stats + copy (side stream) ----------------
__global__ __launch_bounds__(256) void softmax_kernel(const float* __restrict__ outp,
                                                      float* __restrict__ ocopy) {
    int warp = threadIdx.x >> 5, lane = threadIdx.x & 31;
    int row = blockIdx.x * 8 + warp;
    const float4* r4 = (const float4*)(outp + (size_t)row * C);
    float4* w4 = (float4*)(ocopy + (size_t)row * C);
    float4 a[8];
    float m = -INFINITY;
#pragma unroll
    for (int i = 0; i < 8; i++) {
        int j = lane + i * 32;
        if (j < C / 4) {
            float4 x = r4[j]; a[i] = x; w4[j] = x;
            m = fmaxf(m, fmaxf(fmaxf(x.x, x.y), fmaxf(x.z, x.w)));
        }
    }
#pragma unroll
    for (int o = 16; o > 0; o >>= 1) m = fmaxf(m, __shfl_xor_sync(0xffffffffu, m, o));
    float s = 0.f;
#pragma unroll
    for (int i = 0; i < 8; i++) {
        int j = lane + i * 32;
        if (j < C / 4)
            s += __expf(a[i].x - m) + __expf(a[i].y - m) + __expf(a[i].z - m) + __expf(a[i].w - m);
    }
#pragma unroll
    for (int o = 16; o > 0; o >>= 1) s += __shfl_xor_sync(0xffffffffu, s, o);
    if (lane == 0) { g_rmax[row] = m; g_rinv[row] = 1.f / s; }
}

// ---------------- similarities (butterfly) + in-block centroid norms ------
#define SIM_ROWS 32
__global__ __launch_bounds__(256, 2) void sim_kernel(
    const float* __restrict__ f0, const float* __restrict__ f1, const float* __restrict__ f2,
    const float* __restrict__ c0, const float* __restrict__ c1, const float* __restrict__ c2) {
    int mod = blockIdx.y;
    const float* fea = mod == 0 ? f0 : (mod == 1 ? f1 : f2);
    const float* cen = mod == 0 ? c0 : (mod == 1 ? c1 : c2);
    int tid = threadIdx.x;
    int lane = tid & 31, warp = tid >> 5;
    int col = tid * 4;

    float4 cw[KC];
#pragma unroll
    for (int k = 0; k < KC; k++)
        cw[k] = *(const float4*)(cen + (size_t)k * D + col);

    __shared__ float stage[SIM_ROWS][8][16];   // 16 KB
    __shared__ float tot[SIM_ROWS][16];        // 2 KB
    __shared__ float s_cn[KC];

    int vidx = ((lane & 1) ? 8 : 0) | ((lane & 2) ? 4 : 0) |
               ((lane & 4) ? 2 : 0) | ((lane & 8) ? 1 : 0);

    // ---- centroid norms from register-resident tile (reuses machinery) ----
    {
        float v[16];
        v[15] = 0.f;
#pragma unroll
        for (int k = 0; k < KC; k++)
            v[k] = cw[k].x * cw[k].x + cw[k].y * cw[k].y + cw[k].z * cw[k].z + cw[k].w * cw[k].w;
#pragma unroll
        for (int s = 0; s < 4; s++) {
            int d2 = 1 << s, half = 8 >> s;
            bool hi = (lane & d2) != 0;
#pragma unroll
            for (int i = 0; i < half; i++) {
                float send = hi ? v[i] : v[i + half];
                float recv = __shfl_xor_sync(0xffffffffu, send, d2);
                v[i] = (hi ? v[i + half] : v[i]) + recv;
            }
        }
        v[0] += __shfl_xor_sync(0xffffffffu, v[0], 16);
        if (lane < 16) stage[0][warp][vidx] = v[0];
        __syncthreads();
        if (tid < KC) {
            float s = 0.f;
#pragma unroll
            for (int w = 0; w < 8; w++) s += stage[0][w][tid];
            s_cn[tid] = 1.f / fmaxf(sqrtf(s), 1e-12f);
        }
        __syncthreads();
    }

    int row0 = blockIdx.x * SIM_ROWS;
    const float4* fp = (const float4*)(fea + (size_t)row0 * D) + tid;
    float4 f = fp[0];

    // -------- phase A: per-row dots + butterfly, no syncs --------
    for (int rr = 0; rr < SIM_ROWS; rr++) {
        float4 fn;
        if (rr + 1 < SIM_ROWS) fn = fp[(rr + 1) * (D / 4)];

        float v[16];
        v[15] = f.x * f.x + f.y * f.y + f.z * f.z + f.w * f.w;
#pragma unroll
        for (int k = 0; k < KC; k++)
            v[k] = f.x * cw[k].x + f.y * cw[k].y + f.z * cw[k].z + f.w * cw[k].w;

#pragma unroll
        for (int s = 0; s < 4; s++) {
            int d2 = 1 << s, half = 8 >> s;
            bool hi = (lane & d2) != 0;
#pragma unroll
            for (int i = 0; i < half; i++) {
                float send = hi ? v[i] : v[i + half];
                float recv = __shfl_xor_sync(0xffffffffu, send, d2);
                v[i] = (hi ? v[i + half] : v[i]) + recv;
            }
        }
        v[0] += __shfl_xor_sync(0xffffffffu, v[0], 16);

        if (lane < 16) stage[rr][warp][vidx] = v[0];
        f = fn;
    }
    __syncthreads();

    // -------- phase B1: reduce over warps --------
#pragma unroll
    for (int e = tid; e < SIM_ROWS * 16; e += 256) {
        int r = e >> 4, vv = e & 15;
        float s = 0.f;
#pragma unroll
        for (int w = 0; w < 8; w++) s += stage[r][w][vv];
        tot[r][vv] = s;
    }
    __syncthreads();

    // -------- phase B2: finalize, one thread per row (no atomics) --------
    if (tid < SIM_ROWS) {
        int r = tid;
        float fin = 1.f / fmaxf(sqrtf(tot[r][15]), 1e-12f);
        float best = -1e30f; int bi = 0; float sum = 0.f;
#pragma unroll
        for (int k = 0; k < KC; k++) {
            float sim = tot[r][k] * fin * s_cn[k];
            sum += sim;
            if (sim > best) { best = sim; bi = k; }
        }
        g_avg[mod][row0 + r] = sum * (1.0f / KC);
        g_assign[mod][row0 + r] = bi;
    }
}

// ---------------- radix select + attractive (smem-resident, side stream) --
__global__ __launch_bounds__(1024) void select_attr_kernel(int rank0) {
    extern __shared__ unsigned int skeys[];       // 16384 u32 = 64 KB
    __shared__ unsigned int hist[256];
    __shared__ unsigned int sc[256];
    __shared__ unsigned int s_prefix;
    __shared__ int s_rank;
    __shared__ float s_thr;
    __shared__ float sred[32];

    int mod = blockIdx.x;
    const float* avg = g_avg[mod];
    int tid = threadIdx.x;
    int lane = tid & 31, warp = tid >> 5;

#pragma unroll
    for (int i = tid; i < B; i += 1024) {
        unsigned int u = __float_as_uint(avg[i]);
        skeys[i] = (u & 0x80000000u) ? ~u : (u | 0x80000000u);
    }
    if (tid == 0) { s_prefix = 0u; s_rank = rank0; }
    __syncthreads();

    for (int p = 3; p >= 0; p--) {
        if (tid < 256) hist[tid] = 0u;
        __syncthreads();
        unsigned int mask = (p == 3) ? 0u : (0xFFFFFFFFu << ((p + 1) * 8));
        unsigned int pref = s_prefix;
        int r = s_rank;
#pragma unroll
        for (int i = tid; i < B; i += 1024) {
            unsigned int u = skeys[i];
            if ((u & mask) == (pref & mask))
                atomicAdd(&hist[(u >> (p * 8)) & 255u], 1u);
        }
        __syncthreads();
        if (tid < 256) sc[tid] = hist[tid];
        __syncthreads();
#pragma unroll
        for (int off = 1; off < 256; off <<= 1) {
            unsigned int add = 0u;
            if (tid < 256 && tid >= off) add = sc[tid - off];
            __syncthreads();
            if (tid < 256) sc[tid] += add;
            __syncthreads();
        }
        if (tid < 256) {
            unsigned int inc = sc[tid], exc = inc - hist[tid];
            if ((unsigned int)r >= exc && (unsigned int)r < inc) {
                s_prefix = pref | ((unsigned int)tid << (p * 8));
                s_rank = r - (int)exc;
            }
        }
        __syncthreads();
    }
    if (tid == 0) {
        unsigned int u = s_prefix;
        unsigned int bits = (u & 0x80000000u) ? (u ^ 0x80000000u) : ~u;
        s_thr = __uint_as_float(bits);
    }
    __syncthreads();

    float thr = s_thr;
    float s = 0.f;
#pragma unroll
    for (int i = tid; i < B; i += 1024) {
        unsigned int u = skeys[i];
        unsigned int bits = (u & 0x80000000u) ? (u ^ 0x80000000u) : ~u;
        float a = __uint_as_float(bits);
        float w = 1.f / (1.f + expf(-5.0f * (a - thr)));   // ALPHA = 5
        s += w * (1.f - a);
    }
#pragma unroll
    for (int o = 16; o > 0; o >>= 1) s += __shfl_xor_sync(0xffffffffu, s, o);
    if (lane == 0) sred[warp] = s;
    __syncthreads();
    if (tid < 32) {
        float t = sred[tid];
#pragma unroll
        for (int o = 16; o > 0; o >>= 1) t += __shfl_xor_sync(0xffffffffu, t, o);
        if (tid == 0) g_attrpart[mod] = t;    // plain store, no init needed
    }
}

// ---------------- segment partial sums (8-row unroll, MLP=8) --------------
#define SEG_CHUNK 64
__global__ __launch_bounds__(256) void seg_kernel(const float* __restrict__ outp) {
    __shared__ float acc[NMOD * KC * 256];   // 46080 B
    __shared__ int   s_a0[SEG_CHUNK], s_a1[SEG_CHUNK], s_a2[SEG_CHUNK];
    __shared__ float s_rm[SEG_CHUNK], s_ri[SEG_CHUNK];
    int tid = threadIdx.x;
    int c = blockIdx.x * 256 + tid;
    bool valid = c < C;
    for (int j = tid; j < NMOD * KC * 256; j += 256) acc[j] = 0.f;

    int r0 = blockIdx.y * SEG_ROWS;
    int rend = r0 + SEG_ROWS; if (rend > B) rend = B;

    for (int cb = r0; cb < rend; cb += SEG_CHUNK) {
        int clen = rend - cb; if (clen > SEG_CHUNK) clen = SEG_CHUNK;  // 64 or 32
        __syncthreads();
        if (tid < clen) {
            s_a0[tid] = g_assign[0][cb + tid] * 256;
            s_a1[tid] = (KC + g_assign[1][cb + tid]) * 256;
            s_a2[tid] = (2 * KC + g_assign[2][cb + tid]) * 256;
            s_rm[tid] = g_rmax[cb + tid];
            s_ri[tid] = g_rinv[cb + tid];
        }
        __syncthreads();
        if (valid) {
            const float* op = outp + (size_t)cb * C + c;
            for (int rr = 0; rr < clen; rr += 8) {
                float p[8];
#pragma unroll
                for (int j = 0; j < 8; j++)
                    p[j] = op[(size_t)(rr + j) * C];           // 8 loads in flight
#pragma unroll
                for (int j = 0; j < 8; j++)
                    p[j] = __expf(p[j] - s_rm[rr + j]) * s_ri[rr + j];
#pragma unroll
                for (int j = 0; j < 8; j++) {
                    acc[s_a0[rr + j] + tid] += p[j];
                    acc[s_a1[rr + j] + tid] += p[j];
                    acc[s_a2[rr + j] + tid] += p[j];
                }
            }
        }
    }
    __syncthreads();
    if (valid) {
        int by = blockIdx.y;
#pragma unroll
        for (int j = 0; j < NMOD * KC; j++)
            g_part[j][by][c] = acc[j * 256 + tid];             // plain store
    }
}

// ---------------- gated entropy (counts computed in-block) ----------------
__global__ void entropy_kernel() {
    int bk = blockIdx.x;  // 0..44
    int mod = bk / KC, k = bk % KC;
    int tid = threadIdx.x;

    // count cluster members from L2-hot assign array
    int cnt = 0;
    const int* as = g_assign[mod];
    for (int i = tid; i < B; i += 256) cnt += (as[i] == k);
    __shared__ int ci[256];
    ci[tid] = cnt; __syncthreads();
    for (int o = 128; o > 0; o >>= 1) {
        if (tid < o) ci[tid] += ci[tid + o];
        __syncthreads();
    }
    float fcnt = (float)ci[0];
    float inv = 1.f / fmaxf(fcnt, 1.f);

    const float* base = &g_part[bk][0][0];
    float s = 0.f;
    for (int i = tid; i < C; i += 256) {
        float t = 0.f;
#pragma unroll 4
        for (int by = 0; by < SEG_BY; by++) t += base[(size_t)by * CPAD + i];
        float mp = t * inv;
        s += mp * __logf(mp + 1e-8f);
    }
    __shared__ float sm[256];
    sm[tid] = s; __syncthreads();
    for (int o = 128; o > 0; o >>= 1) {
        if (tid < o) sm[tid] += sm[tid + o];
        __syncthreads();
    }
    if (tid == 0) g_entpart[bk] = (fcnt >= 3.0f) ? sm[0] : 0.f;
}

// ---------------- finalize ----------------
__global__ void finalize_kernel(float* dout_last) {
    int lane = threadIdx.x;   // 64 threads
    float s = (lane < NMOD * KC) ? g_entpart[lane] : 0.f;
#pragma unroll
    for (int o = 16; o > 0; o >>= 1) s += __shfl_xor_sync(0xffffffffu, s, o);
    __shared__ float w0, w1;
    if (lane == 0) w0 = s;
    if (lane == 32) w1 = s;
    __syncthreads();
    if (lane == 0) {
        float attr = g_attrpart[0] + g_attrpart[1] + g_attrpart[2];
        // LAM_CLUSTER = 6.0, LAM_DIV = 0.1
        *dout_last = 6.0f * (attr / (float)B) + 0.1f * (w0 + w1);
    }
}

// ---------------- launch: fork-join multi-stream graph --------------------
extern "C" void kernel_launch(void* const* d_in, const int* in_sizes, int n_in,
                              void* d_out, int out_size) {
    const float* f0 = (const float*)d_in[0];
    const float* f1 = (const float*)d_in[1];
    const float* f2 = (const float*)d_in[2];
    const float* c0 = (const float*)d_in[3];
    const float* c1 = (const float*)d_in[4];
    const float* c2 = (const float*)d_in[5];
    const float* outp = (const float*)d_in[6];
    float* dout = (float*)d_out;
    (void)n_in; (void)in_sizes;

    static cudaStream_t s1 = 0, s2 = 0;
    static cudaEvent_t ev_root = 0, ev_sm = 0, ev_sim = 0, ev_sel = 0;
    if (s1 == 0) {
        cudaStreamCreateWithFlags(&s1, cudaStreamNonBlocking);
        cudaStreamCreateWithFlags(&s2, cudaStreamNonBlocking);
        cudaEventCreateWithFlags(&ev_root, cudaEventDisableTiming);
        cudaEventCreateWithFlags(&ev_sm, cudaEventDisableTiming);
        cudaEventCreateWithFlags(&ev_sim, cudaEventDisableTiming);
        cudaEventCreateWithFlags(&ev_sel, cudaEventDisableTiming);
        cudaFuncSetAttribute(select_attr_kernel,
                             cudaFuncAttributeMaxDynamicSharedMemorySize, B * 4);
    }

    // fork: softmax on s1 (independent of sim)
    cudaEventRecord(ev_root, 0);
    cudaStreamWaitEvent(s1, ev_root, 0);
    softmax_kernel<<<B / 8, 256, 0, s1>>>(outp, dout);                      // #1
    cudaEventRecord(ev_sm, s1);

    // main: sim (with fused centroid norms)
    sim_kernel<<<dim3(B / SIM_ROWS, NMOD), 256>>>(f0, f1, f2, c0, c1, c2);  // #2

    // fork: select on s2 (depends only on sim)
    cudaEventRecord(ev_sim, 0);
    cudaStreamWaitEvent(s2, ev_sim, 0);
    int rank0 = B - (int)((double)B * 0.6);   // = 6554
    select_attr_kernel<<<NMOD, 1024, B * 4, s2>>>(rank0);                   // #3
    cudaEventRecord(ev_sel, s2);

    // main: seg needs softmax + sim
    cudaStreamWaitEvent(0, ev_sm, 0);
    seg_kernel<<<dim3(4, SEG_BY), 256>>>(outp);                             // #4 (profiled)
    entropy_kernel<<<NMOD * KC, 256>>>();                                   // #5

    // join select, finalize
    cudaStreamWaitEvent(0, ev_sel, 0);
    finalize_kernel<<<1, 64>>>(dout + (size_t)out_size - 1);                // #6
}